// round 1
// baseline (speedup 1.0000x reference)
#include <cuda_runtime.h>
#include <math_constants.h>
#include <cstdint>

// Problem constants
#define BSZ     2
#define NHEAD   16
#define HDIM    64
#define SEQ     2048
#define EMB     1024
#define MROWS   (BSZ * SEQ)          // 4096

// ---------------------------------------------------------------------------
// Scratch (alloc-free rule: __device__ globals)
// ---------------------------------------------------------------------------
__device__ float g_q[MROWS * EMB];   // Q projection, (b,t,h,d) flattened = (4096,1024)
__device__ float g_k[MROWS * EMB];
__device__ float g_v[MROWS * EMB];
__device__ float g_o[MROWS * EMB];   // attention output, (b,t,h,d)

// ---------------------------------------------------------------------------
// SGEMM (NT): Y[m,n] = sum_k A[m,k] * W[n,k] + bias[n]
// A: MxK row-major, W: NxK row-major. Tiles 128x128x8, 256 threads, 8x8 micro.
// ---------------------------------------------------------------------------
__global__ __launch_bounds__(256) void sgemm_nt(
    const float* __restrict__ A, const float* __restrict__ W,
    const float* __restrict__ bias, float* __restrict__ Y,
    int M, int N, int K)
{
    __shared__ float As[8][128];
    __shared__ float Bs[8][128];

    const int bm = blockIdx.y * 128;
    const int bn = blockIdx.x * 128;
    const int tid = threadIdx.x;
    const int tx = tid & 15;
    const int ty = tid >> 4;
    const int lr = tid >> 1;          // 0..127
    const int lc = (tid & 1) * 4;     // 0 or 4

    const float* Ap = A + (size_t)(bm + lr) * K + lc;
    const float* Wp = W + (size_t)(bn + lr) * K + lc;

    float acc[8][8];
    #pragma unroll
    for (int i = 0; i < 8; i++)
        #pragma unroll
        for (int j = 0; j < 8; j++) acc[i][j] = 0.0f;

    for (int k0 = 0; k0 < K; k0 += 8) {
        float4 a4 = *(const float4*)(Ap + k0);
        float4 b4 = *(const float4*)(Wp + k0);
        As[lc + 0][lr] = a4.x; As[lc + 1][lr] = a4.y;
        As[lc + 2][lr] = a4.z; As[lc + 3][lr] = a4.w;
        Bs[lc + 0][lr] = b4.x; Bs[lc + 1][lr] = b4.y;
        Bs[lc + 2][lr] = b4.z; Bs[lc + 3][lr] = b4.w;
        __syncthreads();

        #pragma unroll
        for (int kk = 0; kk < 8; kk++) {
            float a[8], b[8];
            *(float4*)(a)     = *(const float4*)&As[kk][ty * 8];
            *(float4*)(a + 4) = *(const float4*)&As[kk][ty * 8 + 4];
            *(float4*)(b)     = *(const float4*)&Bs[kk][tx * 8];
            *(float4*)(b + 4) = *(const float4*)&Bs[kk][tx * 8 + 4];
            #pragma unroll
            for (int i = 0; i < 8; i++)
                #pragma unroll
                for (int j = 0; j < 8; j++)
                    acc[i][j] += a[i] * b[j];
        }
        __syncthreads();
    }

    float bb[8];
    *(float4*)(bb)     = *(const float4*)&bias[bn + tx * 8];
    *(float4*)(bb + 4) = *(const float4*)&bias[bn + tx * 8 + 4];

    #pragma unroll
    for (int i = 0; i < 8; i++) {
        float* yp = Y + (size_t)(bm + ty * 8 + i) * N + bn + tx * 8;
        float4 o1 = make_float4(acc[i][0] + bb[0], acc[i][1] + bb[1],
                                acc[i][2] + bb[2], acc[i][3] + bb[3]);
        float4 o2 = make_float4(acc[i][4] + bb[4], acc[i][5] + bb[5],
                                acc[i][6] + bb[6], acc[i][7] + bb[7]);
        *(float4*)(yp)     = o1;
        *(float4*)(yp + 4) = o2;
    }
}

// ---------------------------------------------------------------------------
// Per-(row,head) centering + CLR bias, in place.
// One warp handles one (row, head): 64 values = 2 per lane.
// ---------------------------------------------------------------------------
__global__ __launch_bounds__(256) void center_bias(
    float* __restrict__ X, const float* __restrict__ clr)
{
    const int gwarp = (blockIdx.x * blockDim.x + threadIdx.x) >> 5;
    const int lane  = threadIdx.x & 31;
    if (gwarp >= MROWS * NHEAD) return;
    const int row = gwarp >> 4;
    const int h   = gwarp & 15;

    float* p = X + (size_t)row * EMB + h * HDIM;
    float a = p[lane];
    float b = p[lane + 32];
    float s = a + b;
    #pragma unroll
    for (int off = 16; off > 0; off >>= 1)
        s += __shfl_xor_sync(0xffffffffu, s, off);
    const float mean = s * (1.0f / 64.0f);
    p[lane]      = a - mean + clr[h * HDIM + lane];
    p[lane + 32] = b - mean + clr[h * HDIM + lane + 32];
}

// ---------------------------------------------------------------------------
// fp32 flash attention. Grid: (TQ/64, H, B). 256 threads.
// Q/K smem stored d-major ([d][q]) so QK^T inner loop is float4 + broadcast.
// Online softmax statistics (m, l) live in registers, reduced with 16-lane
// shfl (lanes with equal ty hold one score row).
// smem stride 68 floats = 272B (16B-aligned, conflict-benign).
// ---------------------------------------------------------------------------
#define FA_STRIDE 68
#define FA_SMEM_FLOATS (4 * 64 * FA_STRIDE + 64)

__global__ __launch_bounds__(256) void flash_fp32(
    const float* __restrict__ Q, const float* __restrict__ K,
    const float* __restrict__ V, const unsigned char* __restrict__ mask,
    float* __restrict__ O)
{
    extern __shared__ float sm[];
    float (*Qs)[FA_STRIDE] = (float (*)[FA_STRIDE])(sm);                      // [d][q]
    float (*Ks)[FA_STRIDE] = (float (*)[FA_STRIDE])(sm + 1 * 64 * FA_STRIDE); // [d][k]
    float (*Vs)[FA_STRIDE] = (float (*)[FA_STRIDE])(sm + 2 * 64 * FA_STRIDE); // [k][d]
    float (*Ss)[FA_STRIDE] = (float (*)[FA_STRIDE])(sm + 3 * 64 * FA_STRIDE); // [q][k]
    float* msk = sm + 4 * 64 * FA_STRIDE;                                     // [64]

    const int qt = blockIdx.x;
    const int h  = blockIdx.y;
    const int b  = blockIdx.z;
    const int tid = threadIdx.x;
    const int tx = tid & 15;
    const int ty = tid >> 4;

    const float* Qb = Q + ((size_t)b * SEQ + qt * 64) * EMB + h * HDIM;
    const float* Kb = K + (size_t)b * SEQ * EMB + h * HDIM;
    const float* Vb = V + (size_t)b * SEQ * EMB + h * HDIM;
    const unsigned char* mb = mask + (size_t)b * SEQ;

    // Load Q tile transposed into smem (coalesced on global).
    for (int i = tid; i < 4096; i += 256) {
        const int r = i >> 6, c = i & 63;
        Qs[c][r] = Qb[(size_t)r * EMB + c];
    }

    float acc[4][4];
    float m[4], l[4];
    #pragma unroll
    for (int i = 0; i < 4; i++) {
        m[i] = -CUDART_INF_F;
        l[i] = 0.0f;
        #pragma unroll
        for (int j = 0; j < 4; j++) acc[i][j] = 0.0f;
    }
    __syncthreads();

    for (int kt = 0; kt < SEQ / 64; kt++) {
        const float* Kt = Kb + (size_t)kt * 64 * EMB;
        const float* Vt = Vb + (size_t)kt * 64 * EMB;
        for (int i = tid; i < 4096; i += 256) {
            const int r = i >> 6, c = i & 63;
            Ks[c][r] = Kt[(size_t)r * EMB + c];
            Vs[r][c] = Vt[(size_t)r * EMB + c];
        }
        if (tid < 64)
            msk[tid] = mb[kt * 64 + tid] ? -CUDART_INF_F : 0.0f;
        __syncthreads();

        // S = Q K^T  (per-thread 4x4 microtile)
        float s[4][4];
        #pragma unroll
        for (int i = 0; i < 4; i++)
            #pragma unroll
            for (int j = 0; j < 4; j++) s[i][j] = 0.0f;

        #pragma unroll 16
        for (int d = 0; d < 64; d++) {
            float4 qa = *(const float4*)&Qs[d][ty * 4];
            float4 kb = *(const float4*)&Ks[d][tx * 4];
            const float a[4]  = {qa.x, qa.y, qa.z, qa.w};
            const float bb[4] = {kb.x, kb.y, kb.z, kb.w};
            #pragma unroll
            for (int i = 0; i < 4; i++)
                #pragma unroll
                for (int j = 0; j < 4; j++)
                    s[i][j] += a[i] * bb[j];
        }

        const float mc[4] = {msk[tx * 4 + 0], msk[tx * 4 + 1],
                             msk[tx * 4 + 2], msk[tx * 4 + 3]};
        #pragma unroll
        for (int i = 0; i < 4; i++)
            #pragma unroll
            for (int j = 0; j < 4; j++)
                s[i][j] = s[i][j] * 0.125f + mc[j];   // /sqrt(64), then mask

        // Online softmax per score row (16 lanes with equal ty share a row).
        #pragma unroll
        for (int i = 0; i < 4; i++) {
            float mx = fmaxf(fmaxf(s[i][0], s[i][1]), fmaxf(s[i][2], s[i][3]));
            #pragma unroll
            for (int off = 8; off > 0; off >>= 1)
                mx = fmaxf(mx, __shfl_xor_sync(0xffffffffu, mx, off));
            const float mnew = fmaxf(m[i], mx);
            const float corr = __expf(m[i] - mnew);
            float rs = 0.0f;
            #pragma unroll
            for (int j = 0; j < 4; j++) {
                s[i][j] = __expf(s[i][j] - mnew);
                rs += s[i][j];
            }
            #pragma unroll
            for (int off = 8; off > 0; off >>= 1)
                rs += __shfl_xor_sync(0xffffffffu, rs, off);
            l[i] = l[i] * corr + rs;
            m[i] = mnew;
            #pragma unroll
            for (int j = 0; j < 4; j++) acc[i][j] *= corr;
        }

        // Publish P for the PV product.
        #pragma unroll
        for (int i = 0; i < 4; i++)
            *(float4*)&Ss[ty * 4 + i][tx * 4] =
                make_float4(s[i][0], s[i][1], s[i][2], s[i][3]);
        __syncthreads();

        // O += P V
        #pragma unroll 8
        for (int k = 0; k < 64; k++) {
            float4 vv = *(const float4*)&Vs[k][tx * 4];
            const float vb[4] = {vv.x, vv.y, vv.z, vv.w};
            #pragma unroll
            for (int i = 0; i < 4; i++) {
                const float p = Ss[ty * 4 + i][k];
                #pragma unroll
                for (int j = 0; j < 4; j++)
                    acc[i][j] += p * vb[j];
            }
        }
        __syncthreads();
    }

    // Normalize and store into (b,t,h,d) layout for the output GEMM.
    float* Ob = O + ((size_t)b * SEQ + qt * 64) * EMB + h * HDIM;
    #pragma unroll
    for (int i = 0; i < 4; i++) {
        const float inv = 1.0f / l[i];
        float4 o = make_float4(acc[i][0] * inv, acc[i][1] * inv,
                               acc[i][2] * inv, acc[i][3] * inv);
        *(float4*)&Ob[(size_t)(ty * 4 + i) * EMB + tx * 4] = o;
    }
}

// ---------------------------------------------------------------------------
// Launch
// ---------------------------------------------------------------------------
extern "C" void kernel_launch(void* const* d_in, const int* in_sizes, int n_in,
                              void* d_out, int out_size)
{
    const float* query = (const float*)d_in[0];
    const float* key   = (const float*)d_in[1];
    const float* value = (const float*)d_in[2];
    const unsigned char* kpm = (const unsigned char*)d_in[3];
    const float* Wq = (const float*)d_in[4];
    const float* bq = (const float*)d_in[5];
    const float* Wk = (const float*)d_in[6];
    const float* bk = (const float*)d_in[7];
    const float* Wv = (const float*)d_in[8];
    const float* bv = (const float*)d_in[9];
    const float* Wo = (const float*)d_in[10];
    const float* bo = (const float*)d_in[11];
    const float* clrq = (const float*)d_in[12];
    const float* clrk = (const float*)d_in[13];
    float* out = (float*)d_out;

    float *gq, *gk, *gv, *go;
    cudaGetSymbolAddress((void**)&gq, g_q);
    cudaGetSymbolAddress((void**)&gk, g_k);
    cudaGetSymbolAddress((void**)&gv, g_v);
    cudaGetSymbolAddress((void**)&go, g_o);

    // Flash kernel needs > 48KB dynamic smem (non-stream op, capture-safe).
    cudaFuncSetAttribute(flash_fp32, cudaFuncAttributeMaxDynamicSharedMemorySize,
                         FA_SMEM_FLOATS * (int)sizeof(float));

    const dim3 ggrid(EMB / 128, MROWS / 128);   // (8, 32)

    sgemm_nt<<<ggrid, 256>>>(query, Wq, bq, gq, MROWS, EMB, EMB);
    sgemm_nt<<<ggrid, 256>>>(key,   Wk, bk, gk, MROWS, EMB, EMB);
    sgemm_nt<<<ggrid, 256>>>(value, Wv, bv, gv, MROWS, EMB, EMB);

    const int nwarps = MROWS * NHEAD;              // 65536
    const int cblocks = (nwarps * 32) / 256;       // 8192
    center_bias<<<cblocks, 256>>>(gq, clrq);
    center_bias<<<cblocks, 256>>>(gk, clrk);

    flash_fp32<<<dim3(SEQ / 64, NHEAD, BSZ), 256,
                 FA_SMEM_FLOATS * (int)sizeof(float)>>>(gq, gk, gv, kpm, go);

    sgemm_nt<<<ggrid, 256>>>(go, Wo, bo, out, MROWS, EMB, EMB);
}

// round 2
// speedup vs baseline: 4.6364x; 4.6364x over previous
#include <cuda_runtime.h>
#include <math_constants.h>
#include <cstdint>

#define BSZ     2
#define NHEAD   16
#define HDIM    64
#define SEQ     2048
#define EMB     1024
#define MROWS   (BSZ * SEQ)          // 4096

// ---------------------------------------------------------------------------
// Scratch
// ---------------------------------------------------------------------------
__device__ float g_q[MROWS * EMB];
__device__ float g_k[MROWS * EMB];
__device__ float g_v[MROWS * EMB];
__device__ float g_o[MROWS * EMB];

// ---------------------------------------------------------------------------
// Helpers
// ---------------------------------------------------------------------------
__device__ __forceinline__ uint32_t f2tf32(float x) {
    uint32_t r;
    asm("cvt.rna.tf32.f32 %0, %1;" : "=r"(r) : "f"(x));
    return r;
}

// D += A*B  (m16n8k8, tf32, row.col)
#define MMA_TF32(d, a, b)                                                     \
    asm volatile(                                                             \
        "mma.sync.aligned.m16n8k8.row.col.f32.tf32.tf32.f32 "                 \
        "{%0,%1,%2,%3}, {%4,%5,%6,%7}, {%8,%9}, {%0,%1,%2,%3};"               \
        : "+f"((d)[0]), "+f"((d)[1]), "+f"((d)[2]), "+f"((d)[3])              \
        : "r"((a)[0]), "r"((a)[1]), "r"((a)[2]), "r"((a)[3]),                 \
          "r"((b)[0]), "r"((b)[1]))

// ---------------------------------------------------------------------------
// TF32 GEMM (NT): Y[m,n] = sum_k A[m,k]*W[n,k] + bias[n]
// Optional fused per-head centering + CLR bias (clr != nullptr):
//   y -= mean over the head's 64 cols; y += clr[h*64 + d]
// Tiles 128x128x16. 256 threads = 8 warps, warp tile 32m x 64n.
// ---------------------------------------------------------------------------
#define ASTR 20   // 16 + 4 pad: (20*g + t) % 32 covers all banks

__global__ __launch_bounds__(256, 2) void gemm_tf32(
    const float* __restrict__ A, const float* __restrict__ W,
    const float* __restrict__ bias, const float* __restrict__ clr,
    float* __restrict__ Y, int M, int N, int K)
{
    __shared__ uint32_t As[128][ASTR];
    __shared__ uint32_t Bs[128][ASTR];

    const int bm = blockIdx.y * 128;
    const int bn = blockIdx.x * 128;
    const int tid  = threadIdx.x;
    const int lane = tid & 31;
    const int wid  = tid >> 5;
    const int wm   = (wid >> 1) * 32;     // warp row offset in tile
    const int wn   = (wid & 1) * 64;      // warp col offset in tile
    const int g    = lane >> 2;           // groupID
    const int t    = lane & 3;            // threadID in group

    const int lrow = tid >> 2;            // 0..63
    const int lcol = (tid & 3) * 4;       // 0,4,8,12

    float acc[2][8][4];
    #pragma unroll
    for (int m = 0; m < 2; m++)
        #pragma unroll
        for (int n = 0; n < 8; n++)
            #pragma unroll
            for (int c = 0; c < 4; c++) acc[m][n][c] = 0.0f;

    for (int k0 = 0; k0 < K; k0 += 16) {
        __syncthreads();
        #pragma unroll
        for (int it = 0; it < 2; it++) {
            const int r = lrow + it * 64;
            float4 a4 = *(const float4*)(A + (size_t)(bm + r) * K + k0 + lcol);
            float4 b4 = *(const float4*)(W + (size_t)(bn + r) * K + k0 + lcol);
            As[r][lcol + 0] = f2tf32(a4.x); As[r][lcol + 1] = f2tf32(a4.y);
            As[r][lcol + 2] = f2tf32(a4.z); As[r][lcol + 3] = f2tf32(a4.w);
            Bs[r][lcol + 0] = f2tf32(b4.x); Bs[r][lcol + 1] = f2tf32(b4.y);
            Bs[r][lcol + 2] = f2tf32(b4.z); Bs[r][lcol + 3] = f2tf32(b4.w);
        }
        __syncthreads();

        #pragma unroll
        for (int kk = 0; kk < 16; kk += 8) {
            uint32_t af[2][4], bf[8][2];
            #pragma unroll
            for (int m = 0; m < 2; m++) {
                const int r = wm + m * 16;
                af[m][0] = As[r + g    ][kk + t    ];
                af[m][1] = As[r + g + 8][kk + t    ];
                af[m][2] = As[r + g    ][kk + t + 4];
                af[m][3] = As[r + g + 8][kk + t + 4];
            }
            #pragma unroll
            for (int n = 0; n < 8; n++) {
                const int c = wn + n * 8;
                bf[n][0] = Bs[c + g][kk + t    ];
                bf[n][1] = Bs[c + g][kk + t + 4];
            }
            #pragma unroll
            for (int m = 0; m < 2; m++)
                #pragma unroll
                for (int n = 0; n < 8; n++)
                    MMA_TF32(acc[m][n], af[m], bf[n]);
        }
    }

    // Epilogue: bias (+ optional centering + clr), then store.
    const int h = blockIdx.x * 2 + (wid & 1);   // head for this warp's 64 cols

    #pragma unroll
    for (int m = 0; m < 2; m++) {
        // bias
        #pragma unroll
        for (int n = 0; n < 8; n++) {
            const int c = bn + wn + n * 8 + 2 * t;
            const float b0 = __ldg(&bias[c]);
            const float b1 = __ldg(&bias[c + 1]);
            acc[m][n][0] += b0; acc[m][n][1] += b1;
            acc[m][n][2] += b0; acc[m][n][3] += b1;
        }
        if (clr) {
            float s0 = 0.0f, s1 = 0.0f;
            #pragma unroll
            for (int n = 0; n < 8; n++) {
                s0 += acc[m][n][0] + acc[m][n][1];
                s1 += acc[m][n][2] + acc[m][n][3];
            }
            s0 += __shfl_xor_sync(0xffffffffu, s0, 1);
            s0 += __shfl_xor_sync(0xffffffffu, s0, 2);
            s1 += __shfl_xor_sync(0xffffffffu, s1, 1);
            s1 += __shfl_xor_sync(0xffffffffu, s1, 2);
            const float mean0 = s0 * (1.0f / 64.0f);
            const float mean1 = s1 * (1.0f / 64.0f);
            #pragma unroll
            for (int n = 0; n < 8; n++) {
                const int d = n * 8 + 2 * t;
                const float c0 = __ldg(&clr[h * 64 + d]);
                const float c1 = __ldg(&clr[h * 64 + d + 1]);
                acc[m][n][0] += c0 - mean0; acc[m][n][1] += c1 - mean0;
                acc[m][n][2] += c0 - mean1; acc[m][n][3] += c1 - mean1;
            }
        }
        const int r0 = bm + wm + m * 16 + g;
        #pragma unroll
        for (int n = 0; n < 8; n++) {
            const int c = bn + wn + n * 8 + 2 * t;
            *(float2*)(Y + (size_t)r0 * N + c) =
                make_float2(acc[m][n][0], acc[m][n][1]);
            *(float2*)(Y + (size_t)(r0 + 8) * N + c) =
                make_float2(acc[m][n][2], acc[m][n][3]);
        }
    }
}

// ---------------------------------------------------------------------------
// TF32 flash attention. Block tile: 128 q x 64 k, HDIM=64.
// 8 warps; warp w owns q rows [w*16, w*16+16). Softmax stats in registers,
// reduced over the 4-lane row group. P round-trips through warp-private smem.
// Grid: (SEQ/128, NHEAD, BSZ), 256 threads.
// ---------------------------------------------------------------------------
#define QSTR 68
#define KSTR 68
#define VSTR 72
#define SSTR 68
#define SM_Q  0
#define SM_K  (SM_Q + 128 * QSTR)
#define SM_V  (SM_K + 64 * KSTR)
#define SM_S  (SM_V + 64 * VSTR)
#define SM_M  (SM_S + 128 * SSTR)
#define FA_SMEM_WORDS (SM_M + 64)

__global__ __launch_bounds__(256, 2) void flash_tf32(
    const float* __restrict__ Q, const float* __restrict__ K,
    const float* __restrict__ V, const unsigned char* __restrict__ mask,
    float* __restrict__ O)
{
    extern __shared__ uint32_t sm[];
    uint32_t* Qs = sm + SM_Q;
    uint32_t* Ks = sm + SM_K;
    uint32_t* Vs = sm + SM_V;
    uint32_t* Ss = sm + SM_S;
    float*    msk = (float*)(sm + SM_M);

    const int qt = blockIdx.x;
    const int h  = blockIdx.y;
    const int b  = blockIdx.z;
    const int tid  = threadIdx.x;
    const int lane = tid & 31;
    const int wid  = tid >> 5;
    const int g = lane >> 2;
    const int t = lane & 3;
    const int wq = wid * 16;            // warp's q-row base within tile

    const float* Qb = Q + ((size_t)b * SEQ + qt * 128) * EMB + h * HDIM;
    const float* Kb = K + (size_t)b * SEQ * EMB + h * HDIM;
    const float* Vb = V + (size_t)b * SEQ * EMB + h * HDIM;
    const unsigned char* mb = mask + (size_t)b * SEQ;

    // Load Q tile (128x64), tf32.
    {
        const int r0 = tid >> 4, c = (tid & 15) * 4;
        #pragma unroll
        for (int it = 0; it < 8; it++) {
            const int r = r0 + it * 16;
            float4 v4 = *(const float4*)(Qb + (size_t)r * EMB + c);
            Qs[r * QSTR + c + 0] = f2tf32(v4.x);
            Qs[r * QSTR + c + 1] = f2tf32(v4.y);
            Qs[r * QSTR + c + 2] = f2tf32(v4.z);
            Qs[r * QSTR + c + 3] = f2tf32(v4.w);
        }
    }

    float o[8][4];
    float mrow[2], lrow[2];
    #pragma unroll
    for (int n = 0; n < 8; n++)
        #pragma unroll
        for (int c = 0; c < 4; c++) o[n][c] = 0.0f;
    mrow[0] = mrow[1] = -CUDART_INF_F;
    lrow[0] = lrow[1] = 0.0f;

    for (int kt = 0; kt < SEQ / 64; kt++) {
        __syncthreads();
        {
            const float* Kt = Kb + (size_t)kt * 64 * EMB;
            const float* Vt = Vb + (size_t)kt * 64 * EMB;
            const int r0 = tid >> 4, c = (tid & 15) * 4;
            #pragma unroll
            for (int it = 0; it < 4; it++) {
                const int r = r0 + it * 16;
                float4 kv = *(const float4*)(Kt + (size_t)r * EMB + c);
                float4 vv = *(const float4*)(Vt + (size_t)r * EMB + c);
                Ks[r * KSTR + c + 0] = f2tf32(kv.x);
                Ks[r * KSTR + c + 1] = f2tf32(kv.y);
                Ks[r * KSTR + c + 2] = f2tf32(kv.z);
                Ks[r * KSTR + c + 3] = f2tf32(kv.w);
                Vs[r * VSTR + c + 0] = f2tf32(vv.x);
                Vs[r * VSTR + c + 1] = f2tf32(vv.y);
                Vs[r * VSTR + c + 2] = f2tf32(vv.z);
                Vs[r * VSTR + c + 3] = f2tf32(vv.w);
            }
            if (tid < 64)
                msk[tid] = mb[kt * 64 + tid] ? -CUDART_INF_F : 0.0f;
        }
        __syncthreads();

        // ---- S = Q K^T (16 q-rows x 64 keys per warp) ----
        float s[8][4];
        #pragma unroll
        for (int n = 0; n < 8; n++)
            #pragma unroll
            for (int c = 0; c < 4; c++) s[n][c] = 0.0f;

        #pragma unroll
        for (int kk = 0; kk < 8; kk++) {
            uint32_t af[4];
            af[0] = Qs[(wq + g    ) * QSTR + kk * 8 + t    ];
            af[1] = Qs[(wq + g + 8) * QSTR + kk * 8 + t    ];
            af[2] = Qs[(wq + g    ) * QSTR + kk * 8 + t + 4];
            af[3] = Qs[(wq + g + 8) * QSTR + kk * 8 + t + 4];
            #pragma unroll
            for (int n = 0; n < 8; n++) {
                uint32_t bf[2];
                bf[0] = Ks[(n * 8 + g) * KSTR + kk * 8 + t    ];
                bf[1] = Ks[(n * 8 + g) * KSTR + kk * 8 + t + 4];
                MMA_TF32(s[n], af, bf);
            }
        }

        // scale + mask
        #pragma unroll
        for (int n = 0; n < 8; n++) {
            const float m0 = msk[n * 8 + 2 * t];
            const float m1 = msk[n * 8 + 2 * t + 1];
            s[n][0] = s[n][0] * 0.125f + m0;
            s[n][1] = s[n][1] * 0.125f + m1;
            s[n][2] = s[n][2] * 0.125f + m0;
            s[n][3] = s[n][3] * 0.125f + m1;
        }

        // ---- online softmax (row groups of 4 lanes) ----
        float mx0 = -CUDART_INF_F, mx1 = -CUDART_INF_F;
        #pragma unroll
        for (int n = 0; n < 8; n++) {
            mx0 = fmaxf(mx0, fmaxf(s[n][0], s[n][1]));
            mx1 = fmaxf(mx1, fmaxf(s[n][2], s[n][3]));
        }
        mx0 = fmaxf(mx0, __shfl_xor_sync(0xffffffffu, mx0, 1));
        mx0 = fmaxf(mx0, __shfl_xor_sync(0xffffffffu, mx0, 2));
        mx1 = fmaxf(mx1, __shfl_xor_sync(0xffffffffu, mx1, 1));
        mx1 = fmaxf(mx1, __shfl_xor_sync(0xffffffffu, mx1, 2));

        const float mn0 = fmaxf(mrow[0], mx0);
        const float mn1 = fmaxf(mrow[1], mx1);
        const float cr0 = __expf(mrow[0] - mn0);
        const float cr1 = __expf(mrow[1] - mn1);

        float rs0 = 0.0f, rs1 = 0.0f;
        #pragma unroll
        for (int n = 0; n < 8; n++) {
            s[n][0] = __expf(s[n][0] - mn0);
            s[n][1] = __expf(s[n][1] - mn0);
            s[n][2] = __expf(s[n][2] - mn1);
            s[n][3] = __expf(s[n][3] - mn1);
            rs0 += s[n][0] + s[n][1];
            rs1 += s[n][2] + s[n][3];
        }
        rs0 += __shfl_xor_sync(0xffffffffu, rs0, 1);
        rs0 += __shfl_xor_sync(0xffffffffu, rs0, 2);
        rs1 += __shfl_xor_sync(0xffffffffu, rs1, 1);
        rs1 += __shfl_xor_sync(0xffffffffu, rs1, 2);

        lrow[0] = lrow[0] * cr0 + rs0;
        lrow[1] = lrow[1] * cr1 + rs1;
        mrow[0] = mn0; mrow[1] = mn1;

        #pragma unroll
        for (int n = 0; n < 8; n++) {
            o[n][0] *= cr0; o[n][1] *= cr0;
            o[n][2] *= cr1; o[n][3] *= cr1;
        }

        // ---- publish P (tf32) into warp-private smem rows ----
        #pragma unroll
        for (int n = 0; n < 8; n++) {
            uint2 p0 = make_uint2(f2tf32(s[n][0]), f2tf32(s[n][1]));
            uint2 p1 = make_uint2(f2tf32(s[n][2]), f2tf32(s[n][3]));
            *(uint2*)&Ss[(wq + g    ) * SSTR + n * 8 + 2 * t] = p0;
            *(uint2*)&Ss[(wq + g + 8) * SSTR + n * 8 + 2 * t] = p1;
        }
        __syncwarp();

        // ---- O += P V ----
        #pragma unroll
        for (int kk = 0; kk < 8; kk++) {
            uint32_t af[4];
            af[0] = Ss[(wq + g    ) * SSTR + kk * 8 + t    ];
            af[1] = Ss[(wq + g + 8) * SSTR + kk * 8 + t    ];
            af[2] = Ss[(wq + g    ) * SSTR + kk * 8 + t + 4];
            af[3] = Ss[(wq + g + 8) * SSTR + kk * 8 + t + 4];
            #pragma unroll
            for (int n = 0; n < 8; n++) {
                uint32_t bf[2];
                bf[0] = Vs[(kk * 8 + t    ) * VSTR + n * 8 + g];
                bf[1] = Vs[(kk * 8 + t + 4) * VSTR + n * 8 + g];
                MMA_TF32(o[n], af, bf);
            }
        }
        __syncwarp();
    }

    // ---- normalize + store (b,t,h,d) ----
    const float inv0 = 1.0f / lrow[0];
    const float inv1 = 1.0f / lrow[1];
    float* Ob = O + ((size_t)b * SEQ + qt * 128) * EMB + h * HDIM;
    #pragma unroll
    for (int n = 0; n < 8; n++) {
        const int d = n * 8 + 2 * t;
        *(float2*)(Ob + (size_t)(wq + g) * EMB + d) =
            make_float2(o[n][0] * inv0, o[n][1] * inv0);
        *(float2*)(Ob + (size_t)(wq + g + 8) * EMB + d) =
            make_float2(o[n][2] * inv1, o[n][3] * inv1);
    }
}

// ---------------------------------------------------------------------------
// Launch
// ---------------------------------------------------------------------------
extern "C" void kernel_launch(void* const* d_in, const int* in_sizes, int n_in,
                              void* d_out, int out_size)
{
    const float* query = (const float*)d_in[0];
    const float* key   = (const float*)d_in[1];
    const float* value = (const float*)d_in[2];
    const unsigned char* kpm = (const unsigned char*)d_in[3];
    const float* Wq = (const float*)d_in[4];
    const float* bq = (const float*)d_in[5];
    const float* Wk = (const float*)d_in[6];
    const float* bk = (const float*)d_in[7];
    const float* Wv = (const float*)d_in[8];
    const float* bv = (const float*)d_in[9];
    const float* Wo = (const float*)d_in[10];
    const float* bo = (const float*)d_in[11];
    const float* clrq = (const float*)d_in[12];
    const float* clrk = (const float*)d_in[13];
    float* out = (float*)d_out;

    float *gq, *gk, *gv, *go;
    cudaGetSymbolAddress((void**)&gq, g_q);
    cudaGetSymbolAddress((void**)&gk, g_k);
    cudaGetSymbolAddress((void**)&gv, g_v);
    cudaGetSymbolAddress((void**)&go, g_o);

    cudaFuncSetAttribute(flash_tf32, cudaFuncAttributeMaxDynamicSharedMemorySize,
                         FA_SMEM_WORDS * (int)sizeof(uint32_t));

    const dim3 ggrid(EMB / 128, MROWS / 128);   // (8, 32)

    gemm_tf32<<<ggrid, 256>>>(query, Wq, bq, clrq, gq, MROWS, EMB, EMB);
    gemm_tf32<<<ggrid, 256>>>(key,   Wk, bk, clrk, gk, MROWS, EMB, EMB);
    gemm_tf32<<<ggrid, 256>>>(value, Wv, bv, nullptr, gv, MROWS, EMB, EMB);

    flash_tf32<<<dim3(SEQ / 128, NHEAD, BSZ), 256,
                 FA_SMEM_WORDS * (int)sizeof(uint32_t)>>>(gq, gk, gv, kpm, go);

    gemm_tf32<<<ggrid, 256>>>(go, Wo, bo, nullptr, out, MROWS, EMB, EMB);
}

// round 3
// speedup vs baseline: 8.3789x; 1.8072x over previous
#include <cuda_runtime.h>
#include <cuda_fp16.h>
#include <math_constants.h>
#include <cstdint>

#define BSZ     2
#define NHEAD   16
#define HDIM    64
#define SEQ     2048
#define EMB     1024
#define MROWS   (BSZ * SEQ)          // 4096

// ---------------------------------------------------------------------------
// Scratch (fp16 intermediates)
// ---------------------------------------------------------------------------
__device__ __half g_q[MROWS * EMB];
__device__ __half g_k[MROWS * EMB];
__device__ __half g_v[MROWS * EMB];
__device__ __half g_o[MROWS * EMB];

// ---------------------------------------------------------------------------
// Helpers
// ---------------------------------------------------------------------------
__device__ __forceinline__ uint32_t packh2(float a, float b) {
    __half2 h = __floats2half2_rn(a, b);
    return *(uint32_t*)&h;
}
__device__ __forceinline__ uint32_t smaddr(const void* p) {
    return (uint32_t)__cvta_generic_to_shared(p);
}
__device__ __forceinline__ void ldsm4(uint32_t& r0, uint32_t& r1,
                                      uint32_t& r2, uint32_t& r3, uint32_t a) {
    asm volatile("ldmatrix.sync.aligned.m8n8.x4.shared.b16 {%0,%1,%2,%3}, [%4];"
                 : "=r"(r0), "=r"(r1), "=r"(r2), "=r"(r3) : "r"(a));
}
__device__ __forceinline__ void ldsm4t(uint32_t& r0, uint32_t& r1,
                                       uint32_t& r2, uint32_t& r3, uint32_t a) {
    asm volatile("ldmatrix.sync.aligned.m8n8.x4.trans.shared.b16 {%0,%1,%2,%3}, [%4];"
                 : "=r"(r0), "=r"(r1), "=r"(r2), "=r"(r3) : "r"(a));
}
// D += A*B  (m16n8k16 fp16 in, fp32 acc)
#define MMA_F16(d, a, b0, b1)                                                 \
    asm volatile(                                                             \
        "mma.sync.aligned.m16n8k16.row.col.f32.f16.f16.f32 "                  \
        "{%0,%1,%2,%3}, {%4,%5,%6,%7}, {%8,%9}, {%0,%1,%2,%3};"               \
        : "+f"((d)[0]), "+f"((d)[1]), "+f"((d)[2]), "+f"((d)[3])              \
        : "r"((a)[0]), "r"((a)[1]), "r"((a)[2]), "r"((a)[3]),                 \
          "r"(b0), "r"(b1))

// ---------------------------------------------------------------------------
// FP16 GEMM (NT): Y[m,n] = sum_k A[m,k]*W[n,k] + bias[n]
// Optional fused per-head centering + CLR bias (clr != nullptr).
// Tiles 128x128x16, ping-pong smem + register prefetch. 8 warps, 32m x 64n.
// A_HALF: A is __half (scratch) vs fp32. OUT_HALF: Y is __half vs fp32.
// ---------------------------------------------------------------------------
#define GSH 24   // smem stride (halves): 16 data + 8 pad (48B rows, conflict-free)

template<int A_HALF, int OUT_HALF>
__global__ __launch_bounds__(256, 2) void gemm_f16(
    const void* __restrict__ Av, const float* __restrict__ W,
    const float* __restrict__ bias, const float* __restrict__ clr,
    void* __restrict__ Yv, int M, int N, int K)
{
    __shared__ __half As[2][128 * GSH];
    __shared__ __half Bs[2][128 * GSH];

    const int bm = blockIdx.y * 128;
    const int bn = blockIdx.x * 128;
    const int tid  = threadIdx.x;
    const int lane = tid & 31;
    const int wid  = tid >> 5;
    const int wm   = (wid >> 1) * 32;
    const int wn   = (wid & 1) * 64;
    const int g    = lane >> 2;
    const int t    = lane & 3;

    // gmem load coords
    const int ar0 = tid >> 2,          ac0 = (tid & 3) * 4;          // fp32 path
    const int ar1 = (tid + 256) >> 2,  ac1 = ((tid + 256) & 3) * 4;
    const int hr  = tid >> 1,          hc  = (tid & 1) * 8;          // half path

    // ldmatrix lane addresses (byte offsets within a buffer)
    const uint32_t a_base = smaddr(As);
    const uint32_t b_base = smaddr(Bs);
    const uint32_t aoff = ((wm + (lane & 15)) * GSH + (lane >> 4) * 8) * 2;
    const uint32_t boff = ((wn + (lane & 7) + (lane >> 4) * 8) * GSH
                           + ((lane >> 3) & 1) * 8) * 2;

    const float* Af = (const float*)Av;
    const __half* Ah = (const __half*)Av;

    float acc[2][8][4];
    #pragma unroll
    for (int m = 0; m < 2; m++)
        #pragma unroll
        for (int n = 0; n < 8; n++)
            #pragma unroll
            for (int c = 0; c < 4; c++) acc[m][n][c] = 0.0f;

    // ---- load tile 0 into buffer 0 ----
    if (A_HALF) {
        *(uint4*)&As[0][hr * GSH + hc] =
            *(const uint4*)(Ah + (size_t)(bm + hr) * K + hc);
    } else {
        float4 a0 = *(const float4*)(Af + (size_t)(bm + ar0) * K + ac0);
        float4 a1 = *(const float4*)(Af + (size_t)(bm + ar1) * K + ac1);
        *(uint2*)&As[0][ar0 * GSH + ac0] =
            make_uint2(packh2(a0.x, a0.y), packh2(a0.z, a0.w));
        *(uint2*)&As[0][ar1 * GSH + ac1] =
            make_uint2(packh2(a1.x, a1.y), packh2(a1.z, a1.w));
    }
    {
        float4 b0 = *(const float4*)(W + (size_t)(bn + ar0) * K + ac0);
        float4 b1 = *(const float4*)(W + (size_t)(bn + ar1) * K + ac1);
        *(uint2*)&Bs[0][ar0 * GSH + ac0] =
            make_uint2(packh2(b0.x, b0.y), packh2(b0.z, b0.w));
        *(uint2*)&Bs[0][ar1 * GSH + ac1] =
            make_uint2(packh2(b1.x, b1.y), packh2(b1.z, b1.w));
    }
    __syncthreads();

    const int NT = K / 16;
    for (int kt = 0; kt < NT; kt++) {
        const int cur = kt & 1;
        const int nxt = cur ^ 1;
        const bool pf = (kt + 1 < NT);

        // prefetch next tile into registers
        uint4  ah;
        float4 af0, af1, bf0, bf1;
        if (pf) {
            const int k0 = (kt + 1) * 16;
            if (A_HALF) {
                ah = *(const uint4*)(Ah + (size_t)(bm + hr) * K + k0 + hc);
            } else {
                af0 = *(const float4*)(Af + (size_t)(bm + ar0) * K + k0 + ac0);
                af1 = *(const float4*)(Af + (size_t)(bm + ar1) * K + k0 + ac1);
            }
            bf0 = *(const float4*)(W + (size_t)(bn + ar0) * K + k0 + ac0);
            bf1 = *(const float4*)(W + (size_t)(bn + ar1) * K + k0 + ac1);
        }

        // compute on cur
        {
            const uint32_t ab = a_base + cur * (128 * GSH * 2) + aoff;
            const uint32_t bb = b_base + cur * (128 * GSH * 2) + boff;
            uint32_t a[2][4];
            #pragma unroll
            for (int mi = 0; mi < 2; mi++)
                ldsm4(a[mi][0], a[mi][1], a[mi][2], a[mi][3],
                      ab + mi * 16 * GSH * 2);
            #pragma unroll
            for (int nj = 0; nj < 4; nj++) {
                uint32_t b0, b1, b2, b3;
                ldsm4(b0, b1, b2, b3, bb + nj * 16 * GSH * 2);
                #pragma unroll
                for (int mi = 0; mi < 2; mi++) {
                    MMA_F16(acc[mi][2 * nj],     a[mi], b0, b1);
                    MMA_F16(acc[mi][2 * nj + 1], a[mi], b2, b3);
                }
            }
        }

        if (pf) {
            if (A_HALF) {
                *(uint4*)&As[nxt][hr * GSH + hc] = ah;
            } else {
                *(uint2*)&As[nxt][ar0 * GSH + ac0] =
                    make_uint2(packh2(af0.x, af0.y), packh2(af0.z, af0.w));
                *(uint2*)&As[nxt][ar1 * GSH + ac1] =
                    make_uint2(packh2(af1.x, af1.y), packh2(af1.z, af1.w));
            }
            *(uint2*)&Bs[nxt][ar0 * GSH + ac0] =
                make_uint2(packh2(bf0.x, bf0.y), packh2(bf0.z, bf0.w));
            *(uint2*)&Bs[nxt][ar1 * GSH + ac1] =
                make_uint2(packh2(bf1.x, bf1.y), packh2(bf1.z, bf1.w));
        }
        __syncthreads();
    }

    // ---- epilogue ----
    const int h = blockIdx.x * 2 + (wid & 1);

    #pragma unroll
    for (int m = 0; m < 2; m++) {
        #pragma unroll
        for (int n = 0; n < 8; n++) {
            const int c = bn + wn + n * 8 + 2 * t;
            const float b0 = __ldg(&bias[c]);
            const float b1 = __ldg(&bias[c + 1]);
            acc[m][n][0] += b0; acc[m][n][1] += b1;
            acc[m][n][2] += b0; acc[m][n][3] += b1;
        }
        if (clr) {
            float s0 = 0.0f, s1 = 0.0f;
            #pragma unroll
            for (int n = 0; n < 8; n++) {
                s0 += acc[m][n][0] + acc[m][n][1];
                s1 += acc[m][n][2] + acc[m][n][3];
            }
            s0 += __shfl_xor_sync(0xffffffffu, s0, 1);
            s0 += __shfl_xor_sync(0xffffffffu, s0, 2);
            s1 += __shfl_xor_sync(0xffffffffu, s1, 1);
            s1 += __shfl_xor_sync(0xffffffffu, s1, 2);
            const float mean0 = s0 * (1.0f / 64.0f);
            const float mean1 = s1 * (1.0f / 64.0f);
            #pragma unroll
            for (int n = 0; n < 8; n++) {
                const int d = n * 8 + 2 * t;
                const float c0 = __ldg(&clr[h * 64 + d]);
                const float c1 = __ldg(&clr[h * 64 + d + 1]);
                acc[m][n][0] += c0 - mean0; acc[m][n][1] += c1 - mean0;
                acc[m][n][2] += c0 - mean1; acc[m][n][3] += c1 - mean1;
            }
        }
        const int r0 = bm + wm + m * 16 + g;
        #pragma unroll
        for (int n = 0; n < 8; n++) {
            const int c = bn + wn + n * 8 + 2 * t;
            if (OUT_HALF) {
                __half* Y = (__half*)Yv;
                *(uint32_t*)(Y + (size_t)r0 * N + c) =
                    packh2(acc[m][n][0], acc[m][n][1]);
                *(uint32_t*)(Y + (size_t)(r0 + 8) * N + c) =
                    packh2(acc[m][n][2], acc[m][n][3]);
            } else {
                float* Y = (float*)Yv;
                *(float2*)(Y + (size_t)r0 * N + c) =
                    make_float2(acc[m][n][0], acc[m][n][1]);
                *(float2*)(Y + (size_t)(r0 + 8) * N + c) =
                    make_float2(acc[m][n][2], acc[m][n][3]);
            }
        }
    }
}

// ---------------------------------------------------------------------------
// FP16 flash attention. Block: 128q, tiles of 64 keys, ping-pong K/V smem.
// 8 warps, each owns 16 q-rows. ldmatrix everywhere; P stays in registers
// (accumulator fragment == A fragment after half2 packing).
// Grid: (SEQ/128, NHEAD, BSZ), 256 threads.
// ---------------------------------------------------------------------------
#define FQ 72                         // smem stride (halves), 144B rows
#define FA_Q_HALVES   (128 * FQ)      // 9216
#define FA_KV_HALVES  (64 * FQ)       // 4608 per buffer
#define FA_SMEM_BYTES ((FA_Q_HALVES + 4 * FA_KV_HALVES) * 2 + 2 * 64 * 4)

__global__ __launch_bounds__(256, 2) void flash_f16(
    const __half* __restrict__ Q, const __half* __restrict__ K,
    const __half* __restrict__ V, const unsigned char* __restrict__ mask,
    __half* __restrict__ O)
{
    extern __shared__ __half smh[];
    __half* Qs = smh;                                   // 128 x 64
    __half* Ks = smh + FA_Q_HALVES;                     // 2 x (64 x 64)
    __half* Vs = smh + FA_Q_HALVES + 2 * FA_KV_HALVES;  // 2 x (64 x 64)
    float*  msk = (float*)(smh + FA_Q_HALVES + 4 * FA_KV_HALVES); // 2 x 64

    const int qt = blockIdx.x;
    const int h  = blockIdx.y;
    const int b  = blockIdx.z;
    const int tid  = threadIdx.x;
    const int lane = tid & 31;
    const int wid  = tid >> 5;
    const int g = lane >> 2;
    const int t = lane & 3;
    const int wq = wid * 16;

    const __half* Qb = Q + ((size_t)b * SEQ + qt * 128) * EMB + h * HDIM;
    const __half* Kb = K + (size_t)b * SEQ * EMB + h * HDIM;
    const __half* Vb = V + (size_t)b * SEQ * EMB + h * HDIM;
    const unsigned char* mb = mask + (size_t)b * SEQ;

    // gmem tile-load coords (uint4 = 8 halves)
    const int lr0 = tid >> 3,          lc0 = (tid & 7) * 8;
    const int lr1 = (tid + 256) >> 3,  lc1 = ((tid + 256) & 7) * 8;

    // ---- Q tile (128 x 64) ----
    #pragma unroll
    for (int i = 0; i < 4; i++) {
        const int r = lr0 + i * 32;   // (tid + i*256) >> 3
        *(uint4*)&Qs[r * FQ + lc0] = *(const uint4*)(Qb + (size_t)r * EMB + lc0);
    }

    // ---- K/V tile 0 into buffer 0 ----
    *(uint4*)&Ks[lr0 * FQ + lc0] = *(const uint4*)(Kb + (size_t)lr0 * EMB + lc0);
    *(uint4*)&Ks[lr1 * FQ + lc1] = *(const uint4*)(Kb + (size_t)lr1 * EMB + lc1);
    *(uint4*)&Vs[lr0 * FQ + lc0] = *(const uint4*)(Vb + (size_t)lr0 * EMB + lc0);
    *(uint4*)&Vs[lr1 * FQ + lc1] = *(const uint4*)(Vb + (size_t)lr1 * EMB + lc1);
    if (tid < 64) msk[tid] = mb[tid] ? -CUDART_INF_F : 0.0f;

    // ldmatrix lane addresses (byte offsets)
    const uint32_t q_base = smaddr(Qs)
        + ((wq + (lane & 15)) * FQ + (lane >> 4) * 8) * 2;
    const uint32_t k_lane = (((lane & 7) + (lane >> 4) * 8) * FQ
                             + ((lane >> 3) & 1) * 8) * 2;
    const uint32_t v_lane = (((lane & 7) + ((lane >> 3) & 1) * 8) * FQ
                             + (lane >> 4) * 8) * 2;
    const uint32_t k_base = smaddr(Ks);
    const uint32_t v_base = smaddr(Vs);

    float o_[8][4];
    float mrow[2], lrow[2];
    #pragma unroll
    for (int n = 0; n < 8; n++)
        #pragma unroll
        for (int c = 0; c < 4; c++) o_[n][c] = 0.0f;
    mrow[0] = mrow[1] = -CUDART_INF_F;
    lrow[0] = lrow[1] = 0.0f;

    __syncthreads();

    for (int kt = 0; kt < SEQ / 64; kt++) {
        const int cur = kt & 1;
        const int nxt = cur ^ 1;
        const bool pf = (kt + 1 < SEQ / 64);
        const uint32_t kb = k_base + cur * (FA_KV_HALVES * 2) + k_lane;
        const uint32_t vb = v_base + cur * (FA_KV_HALVES * 2) + v_lane;
        const float* mskc = msk + cur * 64;

        // prefetch next K/V tile
        uint4 kr0, kr1, vr0, vr1;
        float mreg = 0.0f;
        if (pf) {
            const __half* Kt = Kb + (size_t)(kt + 1) * 64 * EMB;
            const __half* Vt = Vb + (size_t)(kt + 1) * 64 * EMB;
            kr0 = *(const uint4*)(Kt + (size_t)lr0 * EMB + lc0);
            kr1 = *(const uint4*)(Kt + (size_t)lr1 * EMB + lc1);
            vr0 = *(const uint4*)(Vt + (size_t)lr0 * EMB + lc0);
            vr1 = *(const uint4*)(Vt + (size_t)lr1 * EMB + lc1);
            if (tid < 64)
                mreg = mb[(kt + 1) * 64 + tid] ? -CUDART_INF_F : 0.0f;
        }

        // ---- S = Q K^T ----
        float s[8][4];
        #pragma unroll
        for (int n = 0; n < 8; n++)
            #pragma unroll
            for (int c = 0; c < 4; c++) s[n][c] = 0.0f;

        #pragma unroll
        for (int kk = 0; kk < 4; kk++) {
            uint32_t a[4];
            ldsm4(a[0], a[1], a[2], a[3], q_base + kk * 32);
            #pragma unroll
            for (int nj = 0; nj < 4; nj++) {
                uint32_t b0, b1, b2, b3;
                ldsm4(b0, b1, b2, b3,
                      kb + nj * (16 * FQ * 2) + kk * 32);
                MMA_F16(s[2 * nj],     a, b0, b1);
                MMA_F16(s[2 * nj + 1], a, b2, b3);
            }
        }

        // scale + mask
        #pragma unroll
        for (int n = 0; n < 8; n++) {
            const float m0 = mskc[n * 8 + 2 * t];
            const float m1 = mskc[n * 8 + 2 * t + 1];
            s[n][0] = s[n][0] * 0.125f + m0;
            s[n][1] = s[n][1] * 0.125f + m1;
            s[n][2] = s[n][2] * 0.125f + m0;
            s[n][3] = s[n][3] * 0.125f + m1;
        }

        // ---- online softmax ----
        float mx0 = -CUDART_INF_F, mx1 = -CUDART_INF_F;
        #pragma unroll
        for (int n = 0; n < 8; n++) {
            mx0 = fmaxf(mx0, fmaxf(s[n][0], s[n][1]));
            mx1 = fmaxf(mx1, fmaxf(s[n][2], s[n][3]));
        }
        mx0 = fmaxf(mx0, __shfl_xor_sync(0xffffffffu, mx0, 1));
        mx0 = fmaxf(mx0, __shfl_xor_sync(0xffffffffu, mx0, 2));
        mx1 = fmaxf(mx1, __shfl_xor_sync(0xffffffffu, mx1, 1));
        mx1 = fmaxf(mx1, __shfl_xor_sync(0xffffffffu, mx1, 2));

        const float mn0 = fmaxf(mrow[0], mx0);
        const float mn1 = fmaxf(mrow[1], mx1);
        const float cr0 = __expf(mrow[0] - mn0);
        const float cr1 = __expf(mrow[1] - mn1);

        float rs0 = 0.0f, rs1 = 0.0f;
        #pragma unroll
        for (int n = 0; n < 8; n++) {
            s[n][0] = __expf(s[n][0] - mn0);
            s[n][1] = __expf(s[n][1] - mn0);
            s[n][2] = __expf(s[n][2] - mn1);
            s[n][3] = __expf(s[n][3] - mn1);
            rs0 += s[n][0] + s[n][1];
            rs1 += s[n][2] + s[n][3];
        }
        rs0 += __shfl_xor_sync(0xffffffffu, rs0, 1);
        rs0 += __shfl_xor_sync(0xffffffffu, rs0, 2);
        rs1 += __shfl_xor_sync(0xffffffffu, rs1, 1);
        rs1 += __shfl_xor_sync(0xffffffffu, rs1, 2);

        lrow[0] = lrow[0] * cr0 + rs0;
        lrow[1] = lrow[1] * cr1 + rs1;
        mrow[0] = mn0; mrow[1] = mn1;

        #pragma unroll
        for (int n = 0; n < 8; n++) {
            o_[n][0] *= cr0; o_[n][1] *= cr0;
            o_[n][2] *= cr1; o_[n][3] *= cr1;
        }

        // ---- pack P into A-fragments (registers only) ----
        uint32_t ph[4][4];
        #pragma unroll
        for (int kk = 0; kk < 4; kk++) {
            ph[kk][0] = packh2(s[2 * kk][0],     s[2 * kk][1]);
            ph[kk][1] = packh2(s[2 * kk][2],     s[2 * kk][3]);
            ph[kk][2] = packh2(s[2 * kk + 1][0], s[2 * kk + 1][1]);
            ph[kk][3] = packh2(s[2 * kk + 1][2], s[2 * kk + 1][3]);
        }

        // ---- O += P V  (V via ldmatrix.trans) ----
        #pragma unroll
        for (int kk = 0; kk < 4; kk++) {
            #pragma unroll
            for (int nj = 0; nj < 4; nj++) {
                uint32_t b0, b1, b2, b3;
                ldsm4t(b0, b1, b2, b3,
                       vb + kk * (16 * FQ * 2) + nj * 32);
                MMA_F16(o_[2 * nj],     ph[kk], b0, b1);
                MMA_F16(o_[2 * nj + 1], ph[kk], b2, b3);
            }
        }

        // ---- stage next tile into smem ----
        if (pf) {
            __half* Kn = Ks + nxt * FA_KV_HALVES;
            __half* Vn = Vs + nxt * FA_KV_HALVES;
            *(uint4*)&Kn[lr0 * FQ + lc0] = kr0;
            *(uint4*)&Kn[lr1 * FQ + lc1] = kr1;
            *(uint4*)&Vn[lr0 * FQ + lc0] = vr0;
            *(uint4*)&Vn[lr1 * FQ + lc1] = vr1;
            if (tid < 64) msk[nxt * 64 + tid] = mreg;
        }
        __syncthreads();
    }

    // ---- normalize + store fp16 (b,t,h,d) ----
    const float inv0 = 1.0f / lrow[0];
    const float inv1 = 1.0f / lrow[1];
    __half* Ob = O + ((size_t)b * SEQ + qt * 128) * EMB + h * HDIM;
    #pragma unroll
    for (int n = 0; n < 8; n++) {
        const int d = n * 8 + 2 * t;
        *(uint32_t*)(Ob + (size_t)(wq + g) * EMB + d) =
            packh2(o_[n][0] * inv0, o_[n][1] * inv0);
        *(uint32_t*)(Ob + (size_t)(wq + g + 8) * EMB + d) =
            packh2(o_[n][2] * inv1, o_[n][3] * inv1);
    }
}

// ---------------------------------------------------------------------------
// Launch
// ---------------------------------------------------------------------------
extern "C" void kernel_launch(void* const* d_in, const int* in_sizes, int n_in,
                              void* d_out, int out_size)
{
    const float* query = (const float*)d_in[0];
    const float* key   = (const float*)d_in[1];
    const float* value = (const float*)d_in[2];
    const unsigned char* kpm = (const unsigned char*)d_in[3];
    const float* Wq = (const float*)d_in[4];
    const float* bq = (const float*)d_in[5];
    const float* Wk = (const float*)d_in[6];
    const float* bk = (const float*)d_in[7];
    const float* Wv = (const float*)d_in[8];
    const float* bv = (const float*)d_in[9];
    const float* Wo = (const float*)d_in[10];
    const float* bo = (const float*)d_in[11];
    const float* clrq = (const float*)d_in[12];
    const float* clrk = (const float*)d_in[13];
    float* out = (float*)d_out;

    __half *gq, *gk, *gv, *go;
    cudaGetSymbolAddress((void**)&gq, g_q);
    cudaGetSymbolAddress((void**)&gk, g_k);
    cudaGetSymbolAddress((void**)&gv, g_v);
    cudaGetSymbolAddress((void**)&go, g_o);

    cudaFuncSetAttribute(flash_f16, cudaFuncAttributeMaxDynamicSharedMemorySize,
                         FA_SMEM_BYTES);

    const dim3 ggrid(EMB / 128, MROWS / 128);   // (8, 32)

    gemm_f16<0, 1><<<ggrid, 256>>>(query, Wq, bq, clrq, gq, MROWS, EMB, EMB);
    gemm_f16<0, 1><<<ggrid, 256>>>(key,   Wk, bk, clrk, gk, MROWS, EMB, EMB);
    gemm_f16<0, 1><<<ggrid, 256>>>(value, Wv, bv, nullptr, gv, MROWS, EMB, EMB);

    flash_f16<<<dim3(SEQ / 128, NHEAD, BSZ), 256, FA_SMEM_BYTES>>>(
        gq, gk, gv, kpm, go);

    gemm_f16<1, 0><<<ggrid, 256>>>(go, Wo, bo, nullptr, out, MROWS, EMB, EMB);
}

// round 4
// speedup vs baseline: 9.0461x; 1.0796x over previous
#include <cuda_runtime.h>
#include <cuda_fp16.h>
#include <math_constants.h>
#include <cstdint>

#define BSZ     2
#define NHEAD   16
#define HDIM    64
#define SEQ     2048
#define EMB     1024
#define MROWS   (BSZ * SEQ)          // 4096

// ---------------------------------------------------------------------------
// Scratch
// ---------------------------------------------------------------------------
__device__ __half g_x0[MROWS * EMB];   // query fp16
__device__ __half g_x1[MROWS * EMB];   // key fp16
__device__ __half g_x2[MROWS * EMB];   // value fp16
__device__ __half g_w0[EMB * EMB];     // Wq fp16
__device__ __half g_w1[EMB * EMB];
__device__ __half g_w2[EMB * EMB];
__device__ __half g_w3[EMB * EMB];     // Wo fp16
__device__ __half g_q[MROWS * EMB];
__device__ __half g_k[MROWS * EMB];
__device__ __half g_v[MROWS * EMB];
__device__ __half g_o[MROWS * EMB];

// ---------------------------------------------------------------------------
// Helpers
// ---------------------------------------------------------------------------
__device__ __forceinline__ uint32_t packh2(float a, float b) {
    __half2 h = __floats2half2_rn(a, b);
    return *(uint32_t*)&h;
}
__device__ __forceinline__ uint32_t smaddr(const void* p) {
    return (uint32_t)__cvta_generic_to_shared(p);
}
__device__ __forceinline__ void ldsm4(uint32_t& r0, uint32_t& r1,
                                      uint32_t& r2, uint32_t& r3, uint32_t a) {
    asm volatile("ldmatrix.sync.aligned.m8n8.x4.shared.b16 {%0,%1,%2,%3}, [%4];"
                 : "=r"(r0), "=r"(r1), "=r"(r2), "=r"(r3) : "r"(a));
}
__device__ __forceinline__ void ldsm4t(uint32_t& r0, uint32_t& r1,
                                       uint32_t& r2, uint32_t& r3, uint32_t a) {
    asm volatile("ldmatrix.sync.aligned.m8n8.x4.trans.shared.b16 {%0,%1,%2,%3}, [%4];"
                 : "=r"(r0), "=r"(r1), "=r"(r2), "=r"(r3) : "r"(a));
}
__device__ __forceinline__ void cpasync16(uint32_t dst, const void* src) {
    asm volatile("cp.async.cg.shared.global [%0], [%1], 16;" :: "r"(dst), "l"(src));
}
#define CP_COMMIT() asm volatile("cp.async.commit_group;")
#define CP_WAIT1()  asm volatile("cp.async.wait_group 1;")
__device__ __forceinline__ float ex2f(float x) {
    float y;
    asm("ex2.approx.ftz.f32 %0, %1;" : "=f"(y) : "f"(x));
    return y;
}
// D += A*B  (m16n8k16 fp16 in, fp32 acc)
#define MMA_F16(d, a, b0, b1)                                                 \
    asm volatile(                                                             \
        "mma.sync.aligned.m16n8k16.row.col.f32.f16.f16.f32 "                  \
        "{%0,%1,%2,%3}, {%4,%5,%6,%7}, {%8,%9}, {%0,%1,%2,%3};"               \
        : "+f"((d)[0]), "+f"((d)[1]), "+f"((d)[2]), "+f"((d)[3])              \
        : "r"((a)[0]), "r"((a)[1]), "r"((a)[2]), "r"((a)[3]),                 \
          "r"(b0), "r"(b1))

// ---------------------------------------------------------------------------
// fp32 -> fp16 bulk conversion. Segments 0-2: 4M floats, 3-6: 1M floats.
// One float4 per thread, grid exactly 4M float4s.
// ---------------------------------------------------------------------------
struct ConvArgs { const float* src[7]; __half* dst[7]; };

__global__ __launch_bounds__(256) void convert_f32_f16(ConvArgs a)
{
    const int idx = blockIdx.x * 256 + threadIdx.x;
    int seg, local;
    if (idx < 3 * 1048576) { seg = idx >> 20;              local = idx & (1048576 - 1); }
    else { const int r = idx - 3 * 1048576; seg = 3 + (r >> 18); local = r & (262144 - 1); }
    const float4 v = ((const float4*)a.src[seg])[local];
    ((uint2*)a.dst[seg])[local] = make_uint2(packh2(v.x, v.y), packh2(v.z, v.w));
}

// ---------------------------------------------------------------------------
// FP16 GEMM (NT), cp.async 3-stage ring: Y = A * W^T + bias (+centering+clr).
// blockIdx.z selects the (A, W, bias, clr, Y) set. Tiles 128x128x16,
// 8 warps (32m x 64n each).
// ---------------------------------------------------------------------------
#define GSH 24                        // smem row stride (halves): 48B rows
#define GBUF (128 * GSH)              // halves per operand per stage

struct GemmArgs {
    const __half* A[3];
    const __half* W[3];
    const float*  bias[3];
    const float*  clr[3];
    void*         Y[3];
};

template<int OUT_HALF>
__global__ __launch_bounds__(256, 2) void gemm_f16(GemmArgs args, int M, int N, int K)
{
    __shared__ __half As[3][GBUF];
    __shared__ __half Bs[3][GBUF];

    const int z = blockIdx.z;
    const __half* A = args.A[z];
    const __half* W = args.W[z];
    const float* bias = args.bias[z];
    const float* clr  = args.clr[z];

    const int bm = blockIdx.y * 128;
    const int bn = blockIdx.x * 128;
    const int tid = threadIdx.x;
    const int lane = tid & 31;
    const int wid  = tid >> 5;
    const int wm = (wid >> 1) * 32;
    const int wn = (wid & 1) * 64;
    const int g = lane >> 2;
    const int t = lane & 3;

    // cp.async coords: one 16B chunk per operand per thread per ktile
    const int row = tid >> 1;
    const int col = (tid & 1) * 8;
    const __half* Ag = A + (size_t)(bm + row) * K + col;
    const __half* Wg = W + (size_t)(bn + row) * K + col;
    const uint32_t sa = smaddr(As) + (row * GSH + col) * 2;
    const uint32_t sb = smaddr(Bs) + (row * GSH + col) * 2;
    const uint32_t BUFB = GBUF * 2;

    // ldmatrix lane addresses
    const uint32_t a_base = smaddr(As) + ((wm + (lane & 15)) * GSH + (lane >> 4) * 8) * 2;
    const uint32_t b_base = smaddr(Bs) + ((wn + (lane & 7) + (lane >> 4) * 8) * GSH
                                          + ((lane >> 3) & 1) * 8) * 2;

    float acc[2][8][4];
    #pragma unroll
    for (int m = 0; m < 2; m++)
        #pragma unroll
        for (int n = 0; n < 8; n++)
            #pragma unroll
            for (int c = 0; c < 4; c++) acc[m][n][c] = 0.0f;

    const int NT = K / 16;

    #define G_ISSUE(kt, buf) {                                   \
        cpasync16(sa + (buf) * BUFB, Ag + (size_t)(kt) * 16);    \
        cpasync16(sb + (buf) * BUFB, Wg + (size_t)(kt) * 16); }

    G_ISSUE(0, 0); CP_COMMIT();
    G_ISSUE(1, 1); CP_COMMIT();
    CP_WAIT1(); __syncthreads();

    int cur = 0, ins = 2;
    for (int kt = 0; kt < NT; kt++) {
        const uint32_t ab = a_base + cur * BUFB;
        const uint32_t bb = b_base + cur * BUFB;
        uint32_t a[2][4];
        #pragma unroll
        for (int mi = 0; mi < 2; mi++)
            ldsm4(a[mi][0], a[mi][1], a[mi][2], a[mi][3], ab + mi * 16 * GSH * 2);
        #pragma unroll
        for (int nj = 0; nj < 4; nj++) {
            uint32_t b0, b1, b2, b3;
            ldsm4(b0, b1, b2, b3, bb + nj * 16 * GSH * 2);
            #pragma unroll
            for (int mi = 0; mi < 2; mi++) {
                MMA_F16(acc[mi][2 * nj],     a[mi], b0, b1);
                MMA_F16(acc[mi][2 * nj + 1], a[mi], b2, b3);
            }
        }

        if (kt + 2 < NT) G_ISSUE(kt + 2, ins);
        CP_COMMIT();
        CP_WAIT1();
        __syncthreads();
        cur = (cur == 2) ? 0 : cur + 1;
        ins = (ins == 2) ? 0 : ins + 1;
    }

    // ---- epilogue ----
    const int h = blockIdx.x * 2 + (wid & 1);

    #pragma unroll
    for (int m = 0; m < 2; m++) {
        #pragma unroll
        for (int n = 0; n < 8; n++) {
            const int c = bn + wn + n * 8 + 2 * t;
            const float b0 = __ldg(&bias[c]);
            const float b1 = __ldg(&bias[c + 1]);
            acc[m][n][0] += b0; acc[m][n][1] += b1;
            acc[m][n][2] += b0; acc[m][n][3] += b1;
        }
        if (clr) {
            float s0 = 0.0f, s1 = 0.0f;
            #pragma unroll
            for (int n = 0; n < 8; n++) {
                s0 += acc[m][n][0] + acc[m][n][1];
                s1 += acc[m][n][2] + acc[m][n][3];
            }
            s0 += __shfl_xor_sync(0xffffffffu, s0, 1);
            s0 += __shfl_xor_sync(0xffffffffu, s0, 2);
            s1 += __shfl_xor_sync(0xffffffffu, s1, 1);
            s1 += __shfl_xor_sync(0xffffffffu, s1, 2);
            const float mean0 = s0 * (1.0f / 64.0f);
            const float mean1 = s1 * (1.0f / 64.0f);
            #pragma unroll
            for (int n = 0; n < 8; n++) {
                const int d = n * 8 + 2 * t;
                const float c0 = __ldg(&clr[h * 64 + d]);
                const float c1 = __ldg(&clr[h * 64 + d + 1]);
                acc[m][n][0] += c0 - mean0; acc[m][n][1] += c1 - mean0;
                acc[m][n][2] += c0 - mean1; acc[m][n][3] += c1 - mean1;
            }
        }
        const int r0 = bm + wm + m * 16 + g;
        #pragma unroll
        for (int n = 0; n < 8; n++) {
            const int c = bn + wn + n * 8 + 2 * t;
            if (OUT_HALF) {
                __half* Y = (__half*)args.Y[z];
                *(uint32_t*)(Y + (size_t)r0 * N + c) =
                    packh2(acc[m][n][0], acc[m][n][1]);
                *(uint32_t*)(Y + (size_t)(r0 + 8) * N + c) =
                    packh2(acc[m][n][2], acc[m][n][3]);
            } else {
                float* Y = (float*)args.Y[z];
                *(float2*)(Y + (size_t)r0 * N + c) =
                    make_float2(acc[m][n][0], acc[m][n][1]);
                *(float2*)(Y + (size_t)(r0 + 8) * N + c) =
                    make_float2(acc[m][n][2], acc[m][n][3]);
            }
        }
    }
}

// ---------------------------------------------------------------------------
// FP16 flash attention, cp.async 3-stage K/V ring, Q fragments hoisted,
// softmax in log2 domain. Block: 128q x 64k, 8 warps (16 q-rows each).
// ---------------------------------------------------------------------------
#define FQ 72                         // smem row stride (halves), 144B rows
#define FA_Q  (128 * FQ)
#define FA_KV (64 * FQ)               // per buffer per tensor
#define FA_SMEM_BYTES ((FA_Q + 6 * FA_KV) * 2 + 3 * 64)
#define CSC 0.18033688011112042f      // 0.125 * log2(e)

__global__ __launch_bounds__(256, 2) void flash_f16(
    const __half* __restrict__ Q, const __half* __restrict__ K,
    const __half* __restrict__ V, const unsigned char* __restrict__ mask,
    __half* __restrict__ O)
{
    extern __shared__ __half smh[];
    __half* Qs = smh;
    __half* Ks = smh + FA_Q;
    __half* Vs = smh + FA_Q + 3 * FA_KV;
    unsigned char* msk = (unsigned char*)(smh + FA_Q + 6 * FA_KV);

    const int qt = blockIdx.x;
    const int h  = blockIdx.y;
    const int b  = blockIdx.z;
    const int tid  = threadIdx.x;
    const int lane = tid & 31;
    const int wid  = tid >> 5;
    const int g = lane >> 2;
    const int t = lane & 3;
    const int wq = wid * 16;

    const __half* Qb = Q + ((size_t)b * SEQ + qt * 128) * EMB + h * HDIM;
    const __half* Kb = K + (size_t)b * SEQ * EMB + h * HDIM;
    const __half* Vb = V + (size_t)b * SEQ * EMB + h * HDIM;
    const unsigned char* mb = mask + (size_t)b * SEQ;

    // cp.async coords (16B chunks, 8 chunks per 64-half row)
    const int lr = tid >> 3;              // 0..31
    const int lc = (tid & 7) * 8;

    // Q tile: 4 chunks/thread
    #pragma unroll
    for (int i = 0; i < 4; i++)
        cpasync16(smaddr(Qs) + (((lr + i * 32) * FQ + lc) * 2),
                  Qb + (size_t)(lr + i * 32) * EMB + lc);

    #define F_ISSUE(kt, buf) {                                                    \
        const __half* Kt = Kb + (size_t)(kt) * 64 * EMB;                          \
        const __half* Vt = Vb + (size_t)(kt) * 64 * EMB;                          \
        const uint32_t ko = smaddr(Ks) + (buf) * (FA_KV * 2);                     \
        const uint32_t vo = smaddr(Vs) + (buf) * (FA_KV * 2);                     \
        cpasync16(ko + (lr * FQ + lc) * 2,        Kt + (size_t)lr * EMB + lc);    \
        cpasync16(ko + ((lr + 32) * FQ + lc) * 2, Kt + (size_t)(lr + 32) * EMB + lc); \
        cpasync16(vo + (lr * FQ + lc) * 2,        Vt + (size_t)lr * EMB + lc);    \
        cpasync16(vo + ((lr + 32) * FQ + lc) * 2, Vt + (size_t)(lr + 32) * EMB + lc); \
        if (tid < 4)                                                              \
            cpasync16(smaddr(msk) + (buf) * 64 + tid * 16, mb + (kt) * 64 + tid * 16); }

    F_ISSUE(0, 0); CP_COMMIT();
    F_ISSUE(1, 1); CP_COMMIT();
    CP_WAIT1(); __syncthreads();

    // hoisted Q fragments
    uint32_t qf[4][4];
    {
        const uint32_t q_base = smaddr(Qs)
            + ((wq + (lane & 15)) * FQ + (lane >> 4) * 8) * 2;
        #pragma unroll
        for (int kk = 0; kk < 4; kk++)
            ldsm4(qf[kk][0], qf[kk][1], qf[kk][2], qf[kk][3], q_base + kk * 32);
    }

    const uint32_t k_lane = (((lane & 7) + (lane >> 4) * 8) * FQ
                             + ((lane >> 3) & 1) * 8) * 2;
    const uint32_t v_lane = (((lane & 7) + ((lane >> 3) & 1) * 8) * FQ
                             + (lane >> 4) * 8) * 2;

    float o_[8][4];
    float mrow[2], lrow[2];
    #pragma unroll
    for (int n = 0; n < 8; n++)
        #pragma unroll
        for (int c = 0; c < 4; c++) o_[n][c] = 0.0f;
    mrow[0] = mrow[1] = -CUDART_INF_F;
    lrow[0] = lrow[1] = 0.0f;

    const int NT = SEQ / 64;
    int cur = 0, ins = 2;
    for (int kt = 0; kt < NT; kt++) {
        const uint32_t kb = smaddr(Ks) + cur * (FA_KV * 2) + k_lane;
        const uint32_t vb = smaddr(Vs) + cur * (FA_KV * 2) + v_lane;
        const unsigned char* mskc = msk + cur * 64;

        // ---- S = Q K^T ----
        float s[8][4];
        #pragma unroll
        for (int n = 0; n < 8; n++)
            #pragma unroll
            for (int c = 0; c < 4; c++) s[n][c] = 0.0f;

        #pragma unroll
        for (int kk = 0; kk < 4; kk++) {
            #pragma unroll
            for (int nj = 0; nj < 4; nj++) {
                uint32_t b0, b1, b2, b3;
                ldsm4(b0, b1, b2, b3, kb + nj * (16 * FQ * 2) + kk * 32);
                MMA_F16(s[2 * nj],     qf[kk], b0, b1);
                MMA_F16(s[2 * nj + 1], qf[kk], b2, b3);
            }
        }

        // scale into log2 domain + mask
        #pragma unroll
        for (int n = 0; n < 8; n++) {
            const float m0 = mskc[n * 8 + 2 * t]     ? -CUDART_INF_F : 0.0f;
            const float m1 = mskc[n * 8 + 2 * t + 1] ? -CUDART_INF_F : 0.0f;
            s[n][0] = s[n][0] * CSC + m0;
            s[n][1] = s[n][1] * CSC + m1;
            s[n][2] = s[n][2] * CSC + m0;
            s[n][3] = s[n][3] * CSC + m1;
        }

        // ---- online softmax (base-2) ----
        float mx0 = -CUDART_INF_F, mx1 = -CUDART_INF_F;
        #pragma unroll
        for (int n = 0; n < 8; n++) {
            mx0 = fmaxf(mx0, fmaxf(s[n][0], s[n][1]));
            mx1 = fmaxf(mx1, fmaxf(s[n][2], s[n][3]));
        }
        mx0 = fmaxf(mx0, __shfl_xor_sync(0xffffffffu, mx0, 1));
        mx0 = fmaxf(mx0, __shfl_xor_sync(0xffffffffu, mx0, 2));
        mx1 = fmaxf(mx1, __shfl_xor_sync(0xffffffffu, mx1, 1));
        mx1 = fmaxf(mx1, __shfl_xor_sync(0xffffffffu, mx1, 2));

        const float mn0 = fmaxf(mrow[0], mx0);
        const float mn1 = fmaxf(mrow[1], mx1);
        const float cr0 = ex2f(mrow[0] - mn0);
        const float cr1 = ex2f(mrow[1] - mn1);

        float rs0 = 0.0f, rs1 = 0.0f;
        #pragma unroll
        for (int n = 0; n < 8; n++) {
            s[n][0] = ex2f(s[n][0] - mn0);
            s[n][1] = ex2f(s[n][1] - mn0);
            s[n][2] = ex2f(s[n][2] - mn1);
            s[n][3] = ex2f(s[n][3] - mn1);
            rs0 += s[n][0] + s[n][1];
            rs1 += s[n][2] + s[n][3];
        }
        rs0 += __shfl_xor_sync(0xffffffffu, rs0, 1);
        rs0 += __shfl_xor_sync(0xffffffffu, rs0, 2);
        rs1 += __shfl_xor_sync(0xffffffffu, rs1, 1);
        rs1 += __shfl_xor_sync(0xffffffffu, rs1, 2);

        lrow[0] = lrow[0] * cr0 + rs0;
        lrow[1] = lrow[1] * cr1 + rs1;
        mrow[0] = mn0; mrow[1] = mn1;

        #pragma unroll
        for (int n = 0; n < 8; n++) {
            o_[n][0] *= cr0; o_[n][1] *= cr0;
            o_[n][2] *= cr1; o_[n][3] *= cr1;
        }

        // ---- pack P into A-fragments (registers only) ----
        uint32_t ph[4][4];
        #pragma unroll
        for (int kk = 0; kk < 4; kk++) {
            ph[kk][0] = packh2(s[2 * kk][0],     s[2 * kk][1]);
            ph[kk][1] = packh2(s[2 * kk][2],     s[2 * kk][3]);
            ph[kk][2] = packh2(s[2 * kk + 1][0], s[2 * kk + 1][1]);
            ph[kk][3] = packh2(s[2 * kk + 1][2], s[2 * kk + 1][3]);
        }

        // ---- O += P V ----
        #pragma unroll
        for (int kk = 0; kk < 4; kk++) {
            #pragma unroll
            for (int nj = 0; nj < 4; nj++) {
                uint32_t b0, b1, b2, b3;
                ldsm4t(b0, b1, b2, b3, vb + kk * (16 * FQ * 2) + nj * 32);
                MMA_F16(o_[2 * nj],     ph[kk], b0, b1);
                MMA_F16(o_[2 * nj + 1], ph[kk], b2, b3);
            }
        }

        if (kt + 2 < NT) F_ISSUE(kt + 2, ins);
        CP_COMMIT();
        CP_WAIT1();
        __syncthreads();
        cur = (cur == 2) ? 0 : cur + 1;
        ins = (ins == 2) ? 0 : ins + 1;
    }

    // ---- normalize + store fp16 (b,t,h,d) ----
    const float inv0 = 1.0f / lrow[0];
    const float inv1 = 1.0f / lrow[1];
    __half* Ob = O + ((size_t)b * SEQ + qt * 128) * EMB + h * HDIM;
    #pragma unroll
    for (int n = 0; n < 8; n++) {
        const int d = n * 8 + 2 * t;
        *(uint32_t*)(Ob + (size_t)(wq + g) * EMB + d) =
            packh2(o_[n][0] * inv0, o_[n][1] * inv0);
        *(uint32_t*)(Ob + (size_t)(wq + g + 8) * EMB + d) =
            packh2(o_[n][2] * inv1, o_[n][3] * inv1);
    }
}

// ---------------------------------------------------------------------------
// Launch
// ---------------------------------------------------------------------------
extern "C" void kernel_launch(void* const* d_in, const int* in_sizes, int n_in,
                              void* d_out, int out_size)
{
    const float* query = (const float*)d_in[0];
    const float* key   = (const float*)d_in[1];
    const float* value = (const float*)d_in[2];
    const unsigned char* kpm = (const unsigned char*)d_in[3];
    const float* Wq = (const float*)d_in[4];
    const float* bq = (const float*)d_in[5];
    const float* Wk = (const float*)d_in[6];
    const float* bk = (const float*)d_in[7];
    const float* Wv = (const float*)d_in[8];
    const float* bv = (const float*)d_in[9];
    const float* Wo = (const float*)d_in[10];
    const float* bo = (const float*)d_in[11];
    const float* clrq = (const float*)d_in[12];
    const float* clrk = (const float*)d_in[13];
    float* out = (float*)d_out;

    __half *x0, *x1, *x2, *w0, *w1, *w2, *w3, *gq, *gk, *gv, *go;
    cudaGetSymbolAddress((void**)&x0, g_x0);
    cudaGetSymbolAddress((void**)&x1, g_x1);
    cudaGetSymbolAddress((void**)&x2, g_x2);
    cudaGetSymbolAddress((void**)&w0, g_w0);
    cudaGetSymbolAddress((void**)&w1, g_w1);
    cudaGetSymbolAddress((void**)&w2, g_w2);
    cudaGetSymbolAddress((void**)&w3, g_w3);
    cudaGetSymbolAddress((void**)&gq, g_q);
    cudaGetSymbolAddress((void**)&gk, g_k);
    cudaGetSymbolAddress((void**)&gv, g_v);
    cudaGetSymbolAddress((void**)&go, g_o);

    cudaFuncSetAttribute(flash_f16, cudaFuncAttributeMaxDynamicSharedMemorySize,
                         FA_SMEM_BYTES);

    // 1) convert everything to fp16
    ConvArgs ca;
    ca.src[0] = query; ca.src[1] = key; ca.src[2] = value;
    ca.src[3] = Wq; ca.src[4] = Wk; ca.src[5] = Wv; ca.src[6] = Wo;
    ca.dst[0] = x0; ca.dst[1] = x1; ca.dst[2] = x2;
    ca.dst[3] = w0; ca.dst[4] = w1; ca.dst[5] = w2; ca.dst[6] = w3;
    convert_f32_f16<<<16384, 256>>>(ca);

    // 2) fused QKV projections (+ centering/clr on Q,K)
    GemmArgs ga;
    ga.A[0] = x0; ga.A[1] = x1; ga.A[2] = x2;
    ga.W[0] = w0; ga.W[1] = w1; ga.W[2] = w2;
    ga.bias[0] = bq; ga.bias[1] = bk; ga.bias[2] = bv;
    ga.clr[0] = clrq; ga.clr[1] = clrk; ga.clr[2] = nullptr;
    ga.Y[0] = gq; ga.Y[1] = gk; ga.Y[2] = gv;
    gemm_f16<1><<<dim3(EMB / 128, MROWS / 128, 3), 256>>>(ga, MROWS, EMB, EMB);

    // 3) attention
    flash_f16<<<dim3(SEQ / 128, NHEAD, BSZ), 256, FA_SMEM_BYTES>>>(
        gq, gk, gv, kpm, go);

    // 4) output projection (fp32 out)
    GemmArgs gb;
    gb.A[0] = go; gb.W[0] = w3; gb.bias[0] = bo; gb.clr[0] = nullptr; gb.Y[0] = out;
    gb.A[1] = gb.A[2] = nullptr; gb.W[1] = gb.W[2] = nullptr;
    gb.bias[1] = gb.bias[2] = nullptr; gb.clr[1] = gb.clr[2] = nullptr;
    gb.Y[1] = gb.Y[2] = nullptr;
    gemm_f16<0><<<dim3(EMB / 128, MROWS / 128, 1), 256>>>(gb, MROWS, EMB, EMB);
}